// round 7
// baseline (speedup 1.0000x reference)
#include <cuda_runtime.h>

#define NBINS 256
#define TPB   256
#define KQ    2              // quads held in registers per thread
#define PAD   32             // ints per counter slot (128B) -> LTS slice spread

__device__ int   g_hist[2 * NBINS * PAD];    // zero-init; re-zeroed each run
__device__ float g_pxmap[NBINS];
__device__ int   g_done0;
__device__ int   g_done1;
__device__ volatile int g_release;

__device__ __forceinline__ int bin_of(float x) {
    return min(max((int)(x * 256.0f), 0), NBINS - 1);
}

// Branchless per-pixel interpolate on the fixed fs grid + clip + rescale-back.
__device__ __forceinline__ float apply1(float x,
                                        const float* __restrict__ fsv,
                                        const float* __restrict__ As,
                                        const float* __restrict__ Bs,
                                        float pm0, float pm255,
                                        float fs0, float fs255) {
    int j = (int)(x * 255.0f) + 1;
    j = min(max(j, 1), NBINS - 1);
    if (fsv[j - 1] > x) --j;          // index guess off by at most 1
    j = max(j, 1);
    if (fsv[j] <= x) ++j;
    j = min(j, NBINS - 1);
    float r = fmaf(As[j], x, Bs[j]);
    if (x <= fs0)   r = pm0;
    if (x >= fs255) r = pm255;
    r = fminf(fmaxf(r, 0.0f), 1.0f);
    return fmaf(r, 255.0f / 127.0f, -1.0f);
}

__global__ void __launch_bounds__(TPB, 4) k_fused(const float* __restrict__ src,
                                                  const float* __restrict__ tgt,
                                                  float* __restrict__ out, int n) {
    __shared__ int   sh[2 * NBINS];
    __shared__ float fsv[NBINS], pmS[NBINS], As[NBINS], Bs[NBINS];
    __shared__ int   is_last;

    const int t    = threadIdx.x;
    const int nth  = gridDim.x * TPB;
    const int gtid = blockIdx.x * TPB + t;
    const int nq   = n >> 2;
    const float SC = 127.0f / 255.0f;

    {   // floating_space: np.arange semantics (f64 i*step -> f32), clipped
        float v = (float)((double)t * (1.0 / 255.0));
        fsv[t] = fminf(fmaxf(v, 0.0f), 1.0f);
    }

    const float4* s4 = (const float4*)src;
    const float4* t4 = (const float4*)tgt;
    float4*       o4 = (float4*)out;

    // ---------------- Phase 1: rescale + global REDG histograms ----------------
    float xr[4 * KQ];

    #pragma unroll
    for (int k = 0; k < KQ; ++k) {
        int q = gtid + k * nth;
        if (q < nq) {
            float4 a = s4[3 * q + 0];
            float4 b = s4[3 * q + 1];
            float4 c = s4[3 * q + 2];
            float4 ta = t4[3 * q + 0];
            float4 tb = t4[3 * q + 1];
            float4 tc = t4[3 * q + 2];

            float x0 = (a.x + 1.0f) * SC, x1 = (a.w + 1.0f) * SC;
            float x2 = (b.z + 1.0f) * SC, x3 = (c.y + 1.0f) * SC;
            xr[4 * k + 0] = x0; xr[4 * k + 1] = x1;
            xr[4 * k + 2] = x2; xr[4 * k + 3] = x3;

            float y0 = (ta.x + 1.0f) * SC * 0.299f + (ta.y + 1.0f) * SC * 0.587f + (ta.z + 1.0f) * SC * 0.114f;
            float y1 = (ta.w + 1.0f) * SC * 0.299f + (tb.x + 1.0f) * SC * 0.587f + (tb.y + 1.0f) * SC * 0.114f;
            float y2 = (tb.z + 1.0f) * SC * 0.299f + (tb.w + 1.0f) * SC * 0.587f + (tc.x + 1.0f) * SC * 0.114f;
            float y3 = (tc.y + 1.0f) * SC * 0.299f + (tc.z + 1.0f) * SC * 0.587f + (tc.w + 1.0f) * SC * 0.114f;

            // fire-and-forget global reductions (RED.E.ADD), 128B-spread slots
            atomicAdd(&g_hist[bin_of(x0) * PAD], 1);
            atomicAdd(&g_hist[(NBINS + bin_of(y0)) * PAD], 1);
            atomicAdd(&g_hist[bin_of(x1) * PAD], 1);
            atomicAdd(&g_hist[(NBINS + bin_of(y1)) * PAD], 1);
            atomicAdd(&g_hist[bin_of(x2) * PAD], 1);
            atomicAdd(&g_hist[(NBINS + bin_of(y2)) * PAD], 1);
            atomicAdd(&g_hist[bin_of(x3) * PAD], 1);
            atomicAdd(&g_hist[(NBINS + bin_of(y3)) * PAD], 1);
        }
    }
    // Overflow quads (n larger than register capacity): spill x to out.
    for (int q = gtid + KQ * nth; q < nq; q += nth) {
        float4 a = s4[3 * q + 0];
        float4 b = s4[3 * q + 1];
        float4 c = s4[3 * q + 2];
        float4 ta = t4[3 * q + 0];
        float4 tb = t4[3 * q + 1];
        float4 tc = t4[3 * q + 2];
        float x0 = (a.x + 1.0f) * SC, x1 = (a.w + 1.0f) * SC;
        float x2 = (b.z + 1.0f) * SC, x3 = (c.y + 1.0f) * SC;
        o4[q] = make_float4(x0, x1, x2, x3);
        float y0 = (ta.x + 1.0f) * SC * 0.299f + (ta.y + 1.0f) * SC * 0.587f + (ta.z + 1.0f) * SC * 0.114f;
        float y1 = (ta.w + 1.0f) * SC * 0.299f + (tb.x + 1.0f) * SC * 0.587f + (tb.y + 1.0f) * SC * 0.114f;
        float y2 = (tb.z + 1.0f) * SC * 0.299f + (tb.w + 1.0f) * SC * 0.587f + (tc.x + 1.0f) * SC * 0.114f;
        float y3 = (tc.y + 1.0f) * SC * 0.299f + (tc.z + 1.0f) * SC * 0.587f + (tc.w + 1.0f) * SC * 0.114f;
        atomicAdd(&g_hist[bin_of(x0) * PAD], 1);
        atomicAdd(&g_hist[(NBINS + bin_of(y0)) * PAD], 1);
        atomicAdd(&g_hist[bin_of(x1) * PAD], 1);
        atomicAdd(&g_hist[(NBINS + bin_of(y1)) * PAD], 1);
        atomicAdd(&g_hist[bin_of(x2) * PAD], 1);
        atomicAdd(&g_hist[(NBINS + bin_of(y2)) * PAD], 1);
        atomicAdd(&g_hist[bin_of(x3) * PAD], 1);
        atomicAdd(&g_hist[(NBINS + bin_of(y3)) * PAD], 1);
    }
    // Tail pixels (n % 4): at most 3, one per thread, x kept in register.
    float xtail = 0.0f;
    const int tidx = 4 * nq + gtid;
    if (tidx < n) {
        xtail = (src[3 * tidx] + 1.0f) * SC;
        atomicAdd(&g_hist[bin_of(xtail) * PAD], 1);
        float yr = (tgt[3 * tidx + 0] + 1.0f) * SC;
        float yg = (tgt[3 * tidx + 1] + 1.0f) * SC;
        float yb = (tgt[3 * tidx + 2] + 1.0f) * SC;
        atomicAdd(&g_hist[(NBINS + bin_of(yr * 0.299f + yg * 0.587f + yb * 0.114f)) * PAD], 1);
    }

    // ---------------- Device-wide barrier ----------------
    __syncthreads();
    if (t == 0) {
        __threadfence();
        int old = atomicAdd(&g_done0, 1);
        is_last = (old == (int)gridDim.x - 1);
    }
    __syncthreads();

    if (is_last) {
        // ---- CDF + pxmap (this block only) ----
        __threadfence();
        sh[t]         = *(volatile int*)&g_hist[t * PAD];
        sh[t + NBINS] = *(volatile int*)&g_hist[(t + NBINS) * PAD];
        __syncthreads();
        #pragma unroll
        for (int off = 1; off < NBINS; off <<= 1) {
            int aself = sh[t], bself = sh[t + NBINS];
            int aprev = (t >= off) ? sh[t - off] : 0;
            int bprev = (t >= off) ? sh[t + NBINS - off] : 0;
            __syncthreads();
            sh[t] = aself + aprev;
            sh[t + NBINS] = bself + bprev;
            __syncthreads();
        }
        {
            int mint = sh[NBINS];
            As[t] = (float)(sh[t + NBINS] - mint) / (float)(n - 1);  // cdftgt
        }
        __syncthreads();
        {
            int mins = sh[0];
            float x = (float)(sh[t] - mins) / (float)(n - 1);        // cdfsrc
            // upper_bound on sorted cdftgt; edges overridden below
            int lo = 0, hi = NBINS - 1;
            while (lo < hi) { int mid = (lo + hi) >> 1; if (As[mid] > x) hi = mid; else lo = mid + 1; }
            int ind1 = lo;
            int ind0 = max(ind1 - 1, 0);
            float dx0 = As[ind0], dx1 = As[ind1];
            float dy0 = fsv[ind0], dy1 = fsv[ind1];
            float dnm = dx1 - dx0;
            float sd  = (dnm == 0.0f) ? 1.0f : dnm;
            float interp = dy0 + (dy1 - dy0) * (x - dx0) / sd;
            float res = (x <= As[0]) ? fsv[0]
                      : ((x >= As[NBINS - 1]) ? fsv[NBINS - 1] : interp);
            pmS[t] = res;
            g_pxmap[t] = res;
        }
        // Zero the histogram slots now (before release; no one reads them again)
        g_hist[t * PAD] = 0;
        g_hist[(t + NBINS) * PAD] = 0;
        __threadfence();
        __syncthreads();
        if (t == 0) g_release = 1;
    } else {
        if (t == 0) {
            while (g_release == 0) __nanosleep(32);
            __threadfence();   // acquire
        }
        __syncthreads();
        pmS[t] = __ldcg(&g_pxmap[t]);
    }
    __syncthreads();

    // ---- slope/intercept tables ----
    if (t > 0) {
        float d = fsv[t] - fsv[t - 1];          // strictly > 0
        float a = (pmS[t] - pmS[t - 1]) / d;
        As[t] = a;
        Bs[t] = pmS[t - 1] - a * fsv[t - 1];
    }
    __syncthreads();

    // ---------------- Phase 3: apply ----------------
    const float pm0 = pmS[0], pm255 = pmS[NBINS - 1];
    const float fs0 = fsv[0], fs255 = fsv[NBINS - 1];

    #pragma unroll
    for (int k = 0; k < KQ; ++k) {
        int q = gtid + k * nth;
        if (q < nq) {
            float4 v;
            v.x = apply1(xr[4 * k + 0], fsv, As, Bs, pm0, pm255, fs0, fs255);
            v.y = apply1(xr[4 * k + 1], fsv, As, Bs, pm0, pm255, fs0, fs255);
            v.z = apply1(xr[4 * k + 2], fsv, As, Bs, pm0, pm255, fs0, fs255);
            v.w = apply1(xr[4 * k + 3], fsv, As, Bs, pm0, pm255, fs0, fs255);
            o4[q] = v;
        }
    }
    for (int q = gtid + KQ * nth; q < nq; q += nth) {
        float4 v = o4[q];   // spilled x values
        v.x = apply1(v.x, fsv, As, Bs, pm0, pm255, fs0, fs255);
        v.y = apply1(v.y, fsv, As, Bs, pm0, pm255, fs0, fs255);
        v.z = apply1(v.z, fsv, As, Bs, pm0, pm255, fs0, fs255);
        v.w = apply1(v.w, fsv, As, Bs, pm0, pm255, fs0, fs255);
        o4[q] = v;
    }
    if (tidx < n) out[tidx] = apply1(xtail, fsv, As, Bs, pm0, pm255, fs0, fs255);

    // ---------------- Reset barrier state for next replay ----------------
    __syncthreads();
    if (t == 0) {
        __threadfence();
        int old = atomicAdd(&g_done1, 1);
        if (old == (int)gridDim.x - 1) {
            g_done0 = 0;
            g_done1 = 0;
            __threadfence();
            g_release = 0;
        }
    }
}

extern "C" void kernel_launch(void* const* d_in, const int* in_sizes, int n_in,
                              void* d_out, int out_size) {
    const float* src = (const float*)d_in[0];
    const float* tgt = (const float*)d_in[1];
    float* out = (float*)d_out;
    int n = in_sizes[0] / 3;   // H*W pixels
    int nq = n >> 2;

    int blocks = (nq + TPB * KQ - 1) / (TPB * KQ);
    if (blocks < 1) blocks = 1;
    if (blocks > 592) blocks = 592;   // co-residency cap: 4 CTAs/SM x 148 SMs

    k_fused<<<blocks, TPB>>>(src, tgt, out, n);
}

// round 8
// speedup vs baseline: 1.8384x; 1.8384x over previous
#include <cuda_runtime.h>

#define NBINS  256
#define TPB    256
#define KQ     2              // quads held in registers per thread
#define NSLOT  32             // per-bin slot spreading for global REDG

// g_slots[0] = src hist slots, g_slots[1] = tgt hist slots.
// Each slot row is 1KB apart -> different LTS hash positions (bit 10+).
__device__ int   g_slots[2][NSLOT][NBINS];   // zero-init; re-zeroed each run
__device__ float g_pxmap[NBINS];
__device__ int   g_done0;
__device__ int   g_done1;
__device__ volatile int g_release;

__device__ __forceinline__ int bin_of(float x) {
    return min(max((int)(x * 256.0f), 0), NBINS - 1);
}

// Branchless per-pixel interpolate on the fixed fs grid + clip + rescale-back.
__device__ __forceinline__ float apply1(float x,
                                        const float* __restrict__ fsv,
                                        const float* __restrict__ As,
                                        const float* __restrict__ Bs,
                                        float pm0, float pm255,
                                        float fs0, float fs255) {
    int j = (int)(x * 255.0f) + 1;
    j = min(max(j, 1), NBINS - 1);
    if (fsv[j - 1] > x) --j;          // index guess off by at most 1
    j = max(j, 1);
    if (fsv[j] <= x) ++j;
    j = min(j, NBINS - 1);
    float r = fmaf(As[j], x, Bs[j]);
    if (x <= fs0)   r = pm0;
    if (x >= fs255) r = pm255;
    r = fminf(fmaxf(r, 0.0f), 1.0f);
    return fmaf(r, 255.0f / 127.0f, -1.0f);
}

__global__ void __launch_bounds__(TPB, 4) k_fused(const float* __restrict__ src,
                                                  const float* __restrict__ tgt,
                                                  float* __restrict__ out, int n) {
    __shared__ int   sh[NBINS];
    __shared__ float fsv[NBINS], pmS[NBINS], As[NBINS], Bs[NBINS];
    __shared__ int   is_last;

    const int t    = threadIdx.x;
    const int wid  = t >> 5;
    const int nth  = gridDim.x * TPB;
    const int gtid = blockIdx.x * TPB + t;
    const int nq   = n >> 2;
    const float SC = 127.0f / 255.0f;
    // tgt REDG slot: varies per (block, warp) -> ~122 increments per address
    const int slot = (blockIdx.x * 8 + wid) & (NSLOT - 1);
    int* tgt_slot = g_slots[1][slot];

    sh[t] = 0;
    {   // floating_space: np.arange semantics (f64 i*step -> f32), clipped
        float v = (float)((double)t * (1.0 / 255.0));
        fsv[t] = fminf(fmaxf(v, 0.0f), 1.0f);
    }
    __syncthreads();

    const float4* s4 = (const float4*)src;
    const float4* t4 = (const float4*)tgt;
    float4*       o4 = (float4*)out;

    // ------------- Phase 1: rescale + split histograms -------------
    // src channel-0 -> shared ATOMS; tgt luma -> global REDG (slot-spread).
    float xr[4 * KQ];

    #pragma unroll
    for (int k = 0; k < KQ; ++k) {
        int q = gtid + k * nth;
        if (q < nq) {
            float4 a = s4[3 * q + 0];
            float4 b = s4[3 * q + 1];
            float4 c = s4[3 * q + 2];
            float4 ta = t4[3 * q + 0];
            float4 tb = t4[3 * q + 1];
            float4 tc = t4[3 * q + 2];

            float x0 = (a.x + 1.0f) * SC, x1 = (a.w + 1.0f) * SC;
            float x2 = (b.z + 1.0f) * SC, x3 = (c.y + 1.0f) * SC;
            xr[4 * k + 0] = x0; xr[4 * k + 1] = x1;
            xr[4 * k + 2] = x2; xr[4 * k + 3] = x3;

            float y0 = (ta.x + 1.0f) * SC * 0.299f + (ta.y + 1.0f) * SC * 0.587f + (ta.z + 1.0f) * SC * 0.114f;
            float y1 = (ta.w + 1.0f) * SC * 0.299f + (tb.x + 1.0f) * SC * 0.587f + (tb.y + 1.0f) * SC * 0.114f;
            float y2 = (tb.z + 1.0f) * SC * 0.299f + (tb.w + 1.0f) * SC * 0.587f + (tc.x + 1.0f) * SC * 0.114f;
            float y3 = (tc.y + 1.0f) * SC * 0.299f + (tc.z + 1.0f) * SC * 0.587f + (tc.w + 1.0f) * SC * 0.114f;

            atomicAdd(&sh[bin_of(x0)], 1);
            atomicAdd(&tgt_slot[bin_of(y0)], 1);   // RED.E.ADD, fire-and-forget
            atomicAdd(&sh[bin_of(x1)], 1);
            atomicAdd(&tgt_slot[bin_of(y1)], 1);
            atomicAdd(&sh[bin_of(x2)], 1);
            atomicAdd(&tgt_slot[bin_of(y2)], 1);
            atomicAdd(&sh[bin_of(x3)], 1);
            atomicAdd(&tgt_slot[bin_of(y3)], 1);
        }
    }
    // Overflow quads (n larger than register capacity): spill x to out.
    for (int q = gtid + KQ * nth; q < nq; q += nth) {
        float4 a = s4[3 * q + 0];
        float4 b = s4[3 * q + 1];
        float4 c = s4[3 * q + 2];
        float4 ta = t4[3 * q + 0];
        float4 tb = t4[3 * q + 1];
        float4 tc = t4[3 * q + 2];
        float x0 = (a.x + 1.0f) * SC, x1 = (a.w + 1.0f) * SC;
        float x2 = (b.z + 1.0f) * SC, x3 = (c.y + 1.0f) * SC;
        o4[q] = make_float4(x0, x1, x2, x3);
        float y0 = (ta.x + 1.0f) * SC * 0.299f + (ta.y + 1.0f) * SC * 0.587f + (ta.z + 1.0f) * SC * 0.114f;
        float y1 = (ta.w + 1.0f) * SC * 0.299f + (tb.x + 1.0f) * SC * 0.587f + (tb.y + 1.0f) * SC * 0.114f;
        float y2 = (tb.z + 1.0f) * SC * 0.299f + (tb.w + 1.0f) * SC * 0.587f + (tc.x + 1.0f) * SC * 0.114f;
        float y3 = (tc.y + 1.0f) * SC * 0.299f + (tc.z + 1.0f) * SC * 0.587f + (tc.w + 1.0f) * SC * 0.114f;
        atomicAdd(&sh[bin_of(x0)], 1);
        atomicAdd(&tgt_slot[bin_of(y0)], 1);
        atomicAdd(&sh[bin_of(x1)], 1);
        atomicAdd(&tgt_slot[bin_of(y1)], 1);
        atomicAdd(&sh[bin_of(x2)], 1);
        atomicAdd(&tgt_slot[bin_of(y2)], 1);
        atomicAdd(&sh[bin_of(x3)], 1);
        atomicAdd(&tgt_slot[bin_of(y3)], 1);
    }
    // Tail pixels (n % 4): at most 3, one per thread, x kept in register.
    float xtail = 0.0f;
    const int tidx = 4 * nq + gtid;
    if (tidx < n) {
        xtail = (src[3 * tidx] + 1.0f) * SC;
        atomicAdd(&sh[bin_of(xtail)], 1);
        float yr = (tgt[3 * tidx + 0] + 1.0f) * SC;
        float yg = (tgt[3 * tidx + 1] + 1.0f) * SC;
        float yb = (tgt[3 * tidx + 2] + 1.0f) * SC;
        atomicAdd(&tgt_slot[bin_of(yr * 0.299f + yg * 0.587f + yb * 0.114f)], 1);
    }

    // flush per-block src hist into slotted global counters (16 ops/addr)
    __syncthreads();
    {
        int v = sh[t];
        if (v) atomicAdd(&g_slots[0][blockIdx.x & (NSLOT - 1)][t], v);
    }

    // ---------------- Device-wide barrier ----------------
    if (t == 0) {
        __threadfence();
        int old = atomicAdd(&g_done0, 1);
        is_last = (old == (int)gridDim.x - 1);
    }
    __syncthreads();

    if (is_last) {
        // ---- reduce slots, CDF + pxmap (this block only) ----
        __threadfence();
        int suma = 0, sumb = 0;
        #pragma unroll
        for (int s = 0; s < NSLOT; ++s) {
            suma += *(volatile int*)&g_slots[0][s][t];
            sumb += *(volatile int*)&g_slots[1][s][t];
            g_slots[0][s][t] = 0;           // re-zero for next replay
            g_slots[1][s][t] = 0;
        }
        __shared__ int sb[NBINS];
        sh[t] = suma;
        sb[t] = sumb;
        __syncthreads();
        #pragma unroll
        for (int off = 1; off < NBINS; off <<= 1) {
            int aself = sh[t], bself = sb[t];
            int aprev = (t >= off) ? sh[t - off] : 0;
            int bprev = (t >= off) ? sb[t - off] : 0;
            __syncthreads();
            sh[t] = aself + aprev;
            sb[t] = bself + bprev;
            __syncthreads();
        }
        {
            int mint = sb[0];
            As[t] = (float)(sb[t] - mint) / (float)(n - 1);   // cdftgt
        }
        __syncthreads();
        {
            int mins = sh[0];
            float x = (float)(sh[t] - mins) / (float)(n - 1); // cdfsrc
            // upper_bound on sorted cdftgt; edges overridden below
            int lo = 0, hi = NBINS - 1;
            while (lo < hi) { int mid = (lo + hi) >> 1; if (As[mid] > x) hi = mid; else lo = mid + 1; }
            int ind1 = lo;
            int ind0 = max(ind1 - 1, 0);
            float dx0 = As[ind0], dx1 = As[ind1];
            float dy0 = fsv[ind0], dy1 = fsv[ind1];
            float dnm = dx1 - dx0;
            float sd  = (dnm == 0.0f) ? 1.0f : dnm;
            float interp = dy0 + (dy1 - dy0) * (x - dx0) / sd;
            float res = (x <= As[0]) ? fsv[0]
                      : ((x >= As[NBINS - 1]) ? fsv[NBINS - 1] : interp);
            pmS[t] = res;
            g_pxmap[t] = res;
        }
        __threadfence();
        __syncthreads();
        if (t == 0) g_release = 1;
    } else {
        if (t == 0) {
            while (g_release == 0) __nanosleep(32);
            __threadfence();   // acquire
        }
        __syncthreads();
        pmS[t] = __ldcg(&g_pxmap[t]);
    }
    __syncthreads();

    // ---- slope/intercept tables ----
    if (t > 0) {
        float d = fsv[t] - fsv[t - 1];          // strictly > 0
        float a = (pmS[t] - pmS[t - 1]) / d;
        As[t] = a;
        Bs[t] = pmS[t - 1] - a * fsv[t - 1];
    }
    __syncthreads();

    // ---------------- Phase 3: apply ----------------
    const float pm0 = pmS[0], pm255 = pmS[NBINS - 1];
    const float fs0 = fsv[0], fs255 = fsv[NBINS - 1];

    #pragma unroll
    for (int k = 0; k < KQ; ++k) {
        int q = gtid + k * nth;
        if (q < nq) {
            float4 v;
            v.x = apply1(xr[4 * k + 0], fsv, As, Bs, pm0, pm255, fs0, fs255);
            v.y = apply1(xr[4 * k + 1], fsv, As, Bs, pm0, pm255, fs0, fs255);
            v.z = apply1(xr[4 * k + 2], fsv, As, Bs, pm0, pm255, fs0, fs255);
            v.w = apply1(xr[4 * k + 3], fsv, As, Bs, pm0, pm255, fs0, fs255);
            o4[q] = v;
        }
    }
    for (int q = gtid + KQ * nth; q < nq; q += nth) {
        float4 v = o4[q];   // spilled x values
        v.x = apply1(v.x, fsv, As, Bs, pm0, pm255, fs0, fs255);
        v.y = apply1(v.y, fsv, As, Bs, pm0, pm255, fs0, fs255);
        v.z = apply1(v.z, fsv, As, Bs, pm0, pm255, fs0, fs255);
        v.w = apply1(v.w, fsv, As, Bs, pm0, pm255, fs0, fs255);
        o4[q] = v;
    }
    if (tidx < n) out[tidx] = apply1(xtail, fsv, As, Bs, pm0, pm255, fs0, fs255);

    // ---------------- Reset barrier state for next replay ----------------
    __syncthreads();
    if (t == 0) {
        __threadfence();
        int old = atomicAdd(&g_done1, 1);
        if (old == (int)gridDim.x - 1) {
            g_done0 = 0;
            g_done1 = 0;
            __threadfence();
            g_release = 0;
        }
    }
}

extern "C" void kernel_launch(void* const* d_in, const int* in_sizes, int n_in,
                              void* d_out, int out_size) {
    const float* src = (const float*)d_in[0];
    const float* tgt = (const float*)d_in[1];
    float* out = (float*)d_out;
    int n = in_sizes[0] / 3;   // H*W pixels
    int nq = n >> 2;

    int blocks = (nq + TPB * KQ - 1) / (TPB * KQ);
    if (blocks < 1) blocks = 1;
    if (blocks > 592) blocks = 592;   // co-residency cap: 4 CTAs/SM x 148 SMs

    k_fused<<<blocks, TPB>>>(src, tgt, out, n);
}

// round 9
// speedup vs baseline: 2.6027x; 1.4157x over previous
#include <cuda_runtime.h>

#define NBINS  256
#define TPB    256
#define KQ     2              // quads held in registers per thread
#define NSLOT  32             // slot spreading for the global flush

// g_slots[0]=src, g_slots[1]=tgt. Flush: block b -> slot b%32 => 16 ops/addr.
__device__ int   g_slots[2][NSLOT][NBINS];   // zero-init; re-zeroed each run
__device__ float g_pxmap[NBINS];
__device__ int   g_done0;
__device__ int   g_done1;
__device__ volatile int g_release;

__device__ __forceinline__ int bin_of(float x) {
    return min(max((int)(x * 256.0f), 0), NBINS - 1);
}

// Branchless per-pixel interpolate on the fixed fs grid + clip + rescale-back.
__device__ __forceinline__ float apply1(float x,
                                        const float* __restrict__ fsv,
                                        const float* __restrict__ As,
                                        const float* __restrict__ Bs,
                                        float pm0, float pm255,
                                        float fs0, float fs255) {
    int j = (int)(x * 255.0f) + 1;
    j = min(max(j, 1), NBINS - 1);
    if (fsv[j - 1] > x) --j;          // index guess off by at most 1
    j = max(j, 1);
    if (fsv[j] <= x) ++j;
    j = min(j, NBINS - 1);
    float r = fmaf(As[j], x, Bs[j]);
    if (x <= fs0)   r = pm0;
    if (x >= fs255) r = pm255;
    r = fminf(fmaxf(r, 0.0f), 1.0f);
    return fmaf(r, 255.0f / 127.0f, -1.0f);
}

__global__ void __launch_bounds__(TPB, 4) k_fused(const float* __restrict__ src,
                                                  const float* __restrict__ tgt,
                                                  float* __restrict__ out, int n) {
    __shared__ int   sha[NBINS], shb[NBINS];
    __shared__ float fsv[NBINS], pmS[NBINS], As[NBINS], Bs[NBINS];
    __shared__ int   is_last;

    const int t    = threadIdx.x;
    const int nth  = gridDim.x * TPB;
    const int gtid = blockIdx.x * TPB + t;
    const int nq   = n >> 2;
    const float SC = 127.0f / 255.0f;

    sha[t] = 0;
    shb[t] = 0;
    {   // floating_space: np.arange semantics (f64 i*step -> f32), clipped
        float v = (float)((double)t * (1.0 / 255.0));
        fsv[t] = fminf(fmaxf(v, 0.0f), 1.0f);
    }
    __syncthreads();

    const float4* s4 = (const float4*)src;
    const float4* t4 = (const float4*)tgt;
    float4*       o4 = (float4*)out;

    // ---------------- Phase 1: rescale + shared-ATOMS histograms ----------------
    float xr[4 * KQ];

    #pragma unroll
    for (int k = 0; k < KQ; ++k) {
        int q = gtid + k * nth;
        if (q < nq) {
            float4 a = s4[3 * q + 0];
            float4 b = s4[3 * q + 1];
            float4 c = s4[3 * q + 2];
            float4 ta = t4[3 * q + 0];
            float4 tb = t4[3 * q + 1];
            float4 tc = t4[3 * q + 2];

            float x0 = (a.x + 1.0f) * SC, x1 = (a.w + 1.0f) * SC;
            float x2 = (b.z + 1.0f) * SC, x3 = (c.y + 1.0f) * SC;
            xr[4 * k + 0] = x0; xr[4 * k + 1] = x1;
            xr[4 * k + 2] = x2; xr[4 * k + 3] = x3;

            float y0 = (ta.x + 1.0f) * SC * 0.299f + (ta.y + 1.0f) * SC * 0.587f + (ta.z + 1.0f) * SC * 0.114f;
            float y1 = (ta.w + 1.0f) * SC * 0.299f + (tb.x + 1.0f) * SC * 0.587f + (tb.y + 1.0f) * SC * 0.114f;
            float y2 = (tb.z + 1.0f) * SC * 0.299f + (tb.w + 1.0f) * SC * 0.587f + (tc.x + 1.0f) * SC * 0.114f;
            float y3 = (tc.y + 1.0f) * SC * 0.299f + (tc.z + 1.0f) * SC * 0.587f + (tc.w + 1.0f) * SC * 0.114f;

            atomicAdd(&sha[bin_of(x0)], 1);
            atomicAdd(&shb[bin_of(y0)], 1);
            atomicAdd(&sha[bin_of(x1)], 1);
            atomicAdd(&shb[bin_of(y1)], 1);
            atomicAdd(&sha[bin_of(x2)], 1);
            atomicAdd(&shb[bin_of(y2)], 1);
            atomicAdd(&sha[bin_of(x3)], 1);
            atomicAdd(&shb[bin_of(y3)], 1);
        }
    }
    // Overflow quads (n larger than register capacity): spill x to out.
    for (int q = gtid + KQ * nth; q < nq; q += nth) {
        float4 a = s4[3 * q + 0];
        float4 b = s4[3 * q + 1];
        float4 c = s4[3 * q + 2];
        float4 ta = t4[3 * q + 0];
        float4 tb = t4[3 * q + 1];
        float4 tc = t4[3 * q + 2];
        float x0 = (a.x + 1.0f) * SC, x1 = (a.w + 1.0f) * SC;
        float x2 = (b.z + 1.0f) * SC, x3 = (c.y + 1.0f) * SC;
        o4[q] = make_float4(x0, x1, x2, x3);
        float y0 = (ta.x + 1.0f) * SC * 0.299f + (ta.y + 1.0f) * SC * 0.587f + (ta.z + 1.0f) * SC * 0.114f;
        float y1 = (ta.w + 1.0f) * SC * 0.299f + (tb.x + 1.0f) * SC * 0.587f + (tb.y + 1.0f) * SC * 0.114f;
        float y2 = (tb.z + 1.0f) * SC * 0.299f + (tb.w + 1.0f) * SC * 0.587f + (tc.x + 1.0f) * SC * 0.114f;
        float y3 = (tc.y + 1.0f) * SC * 0.299f + (tc.z + 1.0f) * SC * 0.587f + (tc.w + 1.0f) * SC * 0.114f;
        atomicAdd(&sha[bin_of(x0)], 1);
        atomicAdd(&shb[bin_of(y0)], 1);
        atomicAdd(&sha[bin_of(x1)], 1);
        atomicAdd(&shb[bin_of(y1)], 1);
        atomicAdd(&sha[bin_of(x2)], 1);
        atomicAdd(&shb[bin_of(y2)], 1);
        atomicAdd(&sha[bin_of(x3)], 1);
        atomicAdd(&shb[bin_of(y3)], 1);
    }
    // Tail pixels (n % 4): at most 3, one per thread, x kept in register.
    float xtail = 0.0f;
    const int tidx = 4 * nq + gtid;
    if (tidx < n) {
        xtail = (src[3 * tidx] + 1.0f) * SC;
        atomicAdd(&sha[bin_of(xtail)], 1);
        float yr = (tgt[3 * tidx + 0] + 1.0f) * SC;
        float yg = (tgt[3 * tidx + 1] + 1.0f) * SC;
        float yb = (tgt[3 * tidx + 2] + 1.0f) * SC;
        atomicAdd(&shb[bin_of(yr * 0.299f + yg * 0.587f + yb * 0.114f)], 1);
    }

    // ---------------- Slotted flush: 16 ops/addr instead of 512 ----------------
    __syncthreads();
    {
        const int slot = blockIdx.x & (NSLOT - 1);
        int va = sha[t];
        int vb = shb[t];
        if (va) atomicAdd(&g_slots[0][slot][t], va);
        if (vb) atomicAdd(&g_slots[1][slot][t], vb);
    }

    // ---------------- Device-wide barrier ----------------
    if (t == 0) {
        __threadfence();
        int old = atomicAdd(&g_done0, 1);
        is_last = (old == (int)gridDim.x - 1);
    }
    __syncthreads();

    if (is_last) {
        // ---- reduce slots (coalesced), CDF + pxmap ----
        __threadfence();
        int suma = 0, sumb = 0;
        #pragma unroll
        for (int s = 0; s < NSLOT; ++s) {
            suma += *(volatile int*)&g_slots[0][s][t];
            sumb += *(volatile int*)&g_slots[1][s][t];
            g_slots[0][s][t] = 0;           // re-zero for next replay
            g_slots[1][s][t] = 0;
        }
        sha[t] = suma;
        shb[t] = sumb;
        __syncthreads();
        #pragma unroll
        for (int off = 1; off < NBINS; off <<= 1) {
            int aself = sha[t], bself = shb[t];
            int aprev = (t >= off) ? sha[t - off] : 0;
            int bprev = (t >= off) ? shb[t - off] : 0;
            __syncthreads();
            sha[t] = aself + aprev;
            shb[t] = bself + bprev;
            __syncthreads();
        }
        {
            int mint = shb[0];
            As[t] = (float)(shb[t] - mint) / (float)(n - 1);   // cdftgt
        }
        __syncthreads();
        {
            int mins = sha[0];
            float x = (float)(sha[t] - mins) / (float)(n - 1); // cdfsrc
            // upper_bound on sorted cdftgt; edges overridden below
            int lo = 0, hi = NBINS - 1;
            while (lo < hi) { int mid = (lo + hi) >> 1; if (As[mid] > x) hi = mid; else lo = mid + 1; }
            int ind1 = lo;
            int ind0 = max(ind1 - 1, 0);
            float dx0 = As[ind0], dx1 = As[ind1];
            float dy0 = fsv[ind0], dy1 = fsv[ind1];
            float dnm = dx1 - dx0;
            float sd  = (dnm == 0.0f) ? 1.0f : dnm;
            float interp = dy0 + (dy1 - dy0) * (x - dx0) / sd;
            float res = (x <= As[0]) ? fsv[0]
                      : ((x >= As[NBINS - 1]) ? fsv[NBINS - 1] : interp);
            pmS[t] = res;
            g_pxmap[t] = res;
        }
        __threadfence();
        __syncthreads();
        if (t == 0) g_release = 1;
    } else {
        if (t == 0) {
            while (g_release == 0) __nanosleep(32);
            __threadfence();   // acquire
        }
        __syncthreads();
        pmS[t] = __ldcg(&g_pxmap[t]);
    }
    __syncthreads();

    // ---- slope/intercept tables ----
    if (t > 0) {
        float d = fsv[t] - fsv[t - 1];          // strictly > 0
        float a = (pmS[t] - pmS[t - 1]) / d;
        As[t] = a;
        Bs[t] = pmS[t - 1] - a * fsv[t - 1];
    }
    __syncthreads();

    // ---------------- Phase 3: apply ----------------
    const float pm0 = pmS[0], pm255 = pmS[NBINS - 1];
    const float fs0 = fsv[0], fs255 = fsv[NBINS - 1];

    #pragma unroll
    for (int k = 0; k < KQ; ++k) {
        int q = gtid + k * nth;
        if (q < nq) {
            float4 v;
            v.x = apply1(xr[4 * k + 0], fsv, As, Bs, pm0, pm255, fs0, fs255);
            v.y = apply1(xr[4 * k + 1], fsv, As, Bs, pm0, pm255, fs0, fs255);
            v.z = apply1(xr[4 * k + 2], fsv, As, Bs, pm0, pm255, fs0, fs255);
            v.w = apply1(xr[4 * k + 3], fsv, As, Bs, pm0, pm255, fs0, fs255);
            o4[q] = v;
        }
    }
    for (int q = gtid + KQ * nth; q < nq; q += nth) {
        float4 v = o4[q];   // spilled x values
        v.x = apply1(v.x, fsv, As, Bs, pm0, pm255, fs0, fs255);
        v.y = apply1(v.y, fsv, As, Bs, pm0, pm255, fs0, fs255);
        v.z = apply1(v.z, fsv, As, Bs, pm0, pm255, fs0, fs255);
        v.w = apply1(v.w, fsv, As, Bs, pm0, pm255, fs0, fs255);
        o4[q] = v;
    }
    if (tidx < n) out[tidx] = apply1(xtail, fsv, As, Bs, pm0, pm255, fs0, fs255);

    // ---------------- Reset barrier state for next replay ----------------
    __syncthreads();
    if (t == 0) {
        __threadfence();
        int old = atomicAdd(&g_done1, 1);
        if (old == (int)gridDim.x - 1) {
            g_done0 = 0;
            g_done1 = 0;
            __threadfence();
            g_release = 0;
        }
    }
}

extern "C" void kernel_launch(void* const* d_in, const int* in_sizes, int n_in,
                              void* d_out, int out_size) {
    const float* src = (const float*)d_in[0];
    const float* tgt = (const float*)d_in[1];
    float* out = (float*)d_out;
    int n = in_sizes[0] / 3;   // H*W pixels
    int nq = n >> 2;

    int blocks = (nq + TPB * KQ - 1) / (TPB * KQ);
    if (blocks < 1) blocks = 1;
    if (blocks > 592) blocks = 592;   // co-residency cap: 4 CTAs/SM x 148 SMs

    k_fused<<<blocks, TPB>>>(src, tgt, out, n);
}

// round 10
// speedup vs baseline: 2.6334x; 1.0118x over previous
#include <cuda_runtime.h>

#define NBINS  256
#define TPB    256
#define KQ     2              // quads held in registers per thread
#define NSLOT  32             // slot spreading for the global flush
#define MAXB   888            // 6 CTAs/SM x 148 SMs

// g_slots[0]=src, g_slots[1]=tgt. Flush: block b -> slot b%32 => ~28 ops/addr.
__device__ int   g_slots[2][NSLOT][NBINS];   // zero-init; re-zeroed each run
__device__ float g_pxmap[NBINS];
__device__ int   g_done0;
__device__ int   g_done1;
__device__ volatile int g_release;

__device__ __forceinline__ int bin_of(float x) {
    return min(max((int)(x * 256.0f), 0), NBINS - 1);
}

// Branchless per-pixel interpolate on the fixed fs grid + clip + rescale-back.
__device__ __forceinline__ float apply1(float x,
                                        const float* __restrict__ fsv,
                                        const float* __restrict__ As,
                                        const float* __restrict__ Bs,
                                        float pm0, float pm255,
                                        float fs0, float fs255) {
    int j = (int)(x * 255.0f) + 1;
    j = min(max(j, 1), NBINS - 1);
    if (fsv[j - 1] > x) --j;          // index guess off by at most 1
    j = max(j, 1);
    if (fsv[j] <= x) ++j;
    j = min(j, NBINS - 1);
    float r = fmaf(As[j], x, Bs[j]);
    if (x <= fs0)   r = pm0;
    if (x >= fs255) r = pm255;
    r = fminf(fmaxf(r, 0.0f), 1.0f);
    return fmaf(r, 255.0f / 127.0f, -1.0f);
}

__global__ void __launch_bounds__(TPB, 6) k_fused(const float* __restrict__ src,
                                                  const float* __restrict__ tgt,
                                                  float* __restrict__ out, int n) {
    __shared__ int   sha[NBINS], shb[NBINS];
    __shared__ float fsv[NBINS], pmS[NBINS], As[NBINS], Bs[NBINS];
    __shared__ int   is_last;

    const int t    = threadIdx.x;
    const int nth  = gridDim.x * TPB;
    const int gtid = blockIdx.x * TPB + t;
    const int nq   = n >> 2;
    const float SC = 127.0f / 255.0f;

    sha[t] = 0;
    shb[t] = 0;
    {   // floating_space: np.arange semantics (f64 i*step -> f32), clipped
        float v = (float)((double)t * (1.0 / 255.0));
        fsv[t] = fminf(fmaxf(v, 0.0f), 1.0f);
    }
    __syncthreads();

    const float4* s4 = (const float4*)src;
    const float4* t4 = (const float4*)tgt;
    float4*       o4 = (float4*)out;

    // ---------------- Phase 1: rescale + shared-ATOMS histograms ----------------
    // Batch ALL loads for both k-iterations before any atomics (MLP=12),
    // so ATOMS drain overlaps outstanding LDG latency.
    float xr[4 * KQ];
    {
        const int q0 = gtid;
        const int q1 = gtid + nth;
        const bool v0 = (q0 < nq);
        const bool v1 = (q1 < nq);

        float4 a0, b0, c0, ta0, tb0, tc0;
        float4 a1, b1, c1, ta1, tb1, tc1;
        if (v0) {
            a0 = s4[3 * q0 + 0]; b0 = s4[3 * q0 + 1]; c0 = s4[3 * q0 + 2];
            ta0 = t4[3 * q0 + 0]; tb0 = t4[3 * q0 + 1]; tc0 = t4[3 * q0 + 2];
        }
        if (v1) {
            a1 = s4[3 * q1 + 0]; b1 = s4[3 * q1 + 1]; c1 = s4[3 * q1 + 2];
            ta1 = t4[3 * q1 + 0]; tb1 = t4[3 * q1 + 1]; tc1 = t4[3 * q1 + 2];
        }

        if (v0) {
            float x0 = (a0.x + 1.0f) * SC, x1 = (a0.w + 1.0f) * SC;
            float x2 = (b0.z + 1.0f) * SC, x3 = (c0.y + 1.0f) * SC;
            xr[0] = x0; xr[1] = x1; xr[2] = x2; xr[3] = x3;
            float y0 = (ta0.x + 1.0f) * SC * 0.299f + (ta0.y + 1.0f) * SC * 0.587f + (ta0.z + 1.0f) * SC * 0.114f;
            float y1 = (ta0.w + 1.0f) * SC * 0.299f + (tb0.x + 1.0f) * SC * 0.587f + (tb0.y + 1.0f) * SC * 0.114f;
            float y2 = (tb0.z + 1.0f) * SC * 0.299f + (tb0.w + 1.0f) * SC * 0.587f + (tc0.x + 1.0f) * SC * 0.114f;
            float y3 = (tc0.y + 1.0f) * SC * 0.299f + (tc0.z + 1.0f) * SC * 0.587f + (tc0.w + 1.0f) * SC * 0.114f;
            atomicAdd(&sha[bin_of(x0)], 1);
            atomicAdd(&shb[bin_of(y0)], 1);
            atomicAdd(&sha[bin_of(x1)], 1);
            atomicAdd(&shb[bin_of(y1)], 1);
            atomicAdd(&sha[bin_of(x2)], 1);
            atomicAdd(&shb[bin_of(y2)], 1);
            atomicAdd(&sha[bin_of(x3)], 1);
            atomicAdd(&shb[bin_of(y3)], 1);
        }
        if (v1) {
            float x0 = (a1.x + 1.0f) * SC, x1 = (a1.w + 1.0f) * SC;
            float x2 = (b1.z + 1.0f) * SC, x3 = (c1.y + 1.0f) * SC;
            xr[4] = x0; xr[5] = x1; xr[6] = x2; xr[7] = x3;
            float y0 = (ta1.x + 1.0f) * SC * 0.299f + (ta1.y + 1.0f) * SC * 0.587f + (ta1.z + 1.0f) * SC * 0.114f;
            float y1 = (ta1.w + 1.0f) * SC * 0.299f + (tb1.x + 1.0f) * SC * 0.587f + (tb1.y + 1.0f) * SC * 0.114f;
            float y2 = (tb1.z + 1.0f) * SC * 0.299f + (tb1.w + 1.0f) * SC * 0.587f + (tc1.x + 1.0f) * SC * 0.114f;
            float y3 = (tc1.y + 1.0f) * SC * 0.299f + (tc1.z + 1.0f) * SC * 0.587f + (tc1.w + 1.0f) * SC * 0.114f;
            atomicAdd(&sha[bin_of(x0)], 1);
            atomicAdd(&shb[bin_of(y0)], 1);
            atomicAdd(&sha[bin_of(x1)], 1);
            atomicAdd(&shb[bin_of(y1)], 1);
            atomicAdd(&sha[bin_of(x2)], 1);
            atomicAdd(&shb[bin_of(y2)], 1);
            atomicAdd(&sha[bin_of(x3)], 1);
            atomicAdd(&shb[bin_of(y3)], 1);
        }
    }
    // Overflow quads (n larger than register capacity): spill x to out.
    for (int q = gtid + KQ * nth; q < nq; q += nth) {
        float4 a = s4[3 * q + 0];
        float4 b = s4[3 * q + 1];
        float4 c = s4[3 * q + 2];
        float4 ta = t4[3 * q + 0];
        float4 tb = t4[3 * q + 1];
        float4 tc = t4[3 * q + 2];
        float x0 = (a.x + 1.0f) * SC, x1 = (a.w + 1.0f) * SC;
        float x2 = (b.z + 1.0f) * SC, x3 = (c.y + 1.0f) * SC;
        o4[q] = make_float4(x0, x1, x2, x3);
        float y0 = (ta.x + 1.0f) * SC * 0.299f + (ta.y + 1.0f) * SC * 0.587f + (ta.z + 1.0f) * SC * 0.114f;
        float y1 = (ta.w + 1.0f) * SC * 0.299f + (tb.x + 1.0f) * SC * 0.587f + (tb.y + 1.0f) * SC * 0.114f;
        float y2 = (tb.z + 1.0f) * SC * 0.299f + (tb.w + 1.0f) * SC * 0.587f + (tc.x + 1.0f) * SC * 0.114f;
        float y3 = (tc.y + 1.0f) * SC * 0.299f + (tc.z + 1.0f) * SC * 0.587f + (tc.w + 1.0f) * SC * 0.114f;
        atomicAdd(&sha[bin_of(x0)], 1);
        atomicAdd(&shb[bin_of(y0)], 1);
        atomicAdd(&sha[bin_of(x1)], 1);
        atomicAdd(&shb[bin_of(y1)], 1);
        atomicAdd(&sha[bin_of(x2)], 1);
        atomicAdd(&shb[bin_of(y2)], 1);
        atomicAdd(&sha[bin_of(x3)], 1);
        atomicAdd(&shb[bin_of(y3)], 1);
    }
    // Tail pixels (n % 4): at most 3, one per thread, x kept in register.
    float xtail = 0.0f;
    const int tidx = 4 * nq + gtid;
    if (tidx < n) {
        xtail = (src[3 * tidx] + 1.0f) * SC;
        atomicAdd(&sha[bin_of(xtail)], 1);
        float yr = (tgt[3 * tidx + 0] + 1.0f) * SC;
        float yg = (tgt[3 * tidx + 1] + 1.0f) * SC;
        float yb = (tgt[3 * tidx + 2] + 1.0f) * SC;
        atomicAdd(&shb[bin_of(yr * 0.299f + yg * 0.587f + yb * 0.114f)], 1);
    }

    // ---------------- Slotted flush ----------------
    __syncthreads();
    {
        const int slot = blockIdx.x & (NSLOT - 1);
        int va = sha[t];
        int vb = shb[t];
        if (va) atomicAdd(&g_slots[0][slot][t], va);
        if (vb) atomicAdd(&g_slots[1][slot][t], vb);
    }

    // ---------------- Device-wide barrier ----------------
    if (t == 0) {
        __threadfence();
        int old = atomicAdd(&g_done0, 1);
        is_last = (old == (int)gridDim.x - 1);
    }
    __syncthreads();

    if (is_last) {
        // ---- reduce slots (coalesced), CDF + pxmap ----
        __threadfence();
        int suma = 0, sumb = 0;
        #pragma unroll
        for (int s = 0; s < NSLOT; ++s) {
            suma += *(volatile int*)&g_slots[0][s][t];
            sumb += *(volatile int*)&g_slots[1][s][t];
            g_slots[0][s][t] = 0;           // re-zero for next replay
            g_slots[1][s][t] = 0;
        }
        sha[t] = suma;
        shb[t] = sumb;
        __syncthreads();
        #pragma unroll
        for (int off = 1; off < NBINS; off <<= 1) {
            int aself = sha[t], bself = shb[t];
            int aprev = (t >= off) ? sha[t - off] : 0;
            int bprev = (t >= off) ? shb[t - off] : 0;
            __syncthreads();
            sha[t] = aself + aprev;
            shb[t] = bself + bprev;
            __syncthreads();
        }
        {
            int mint = shb[0];
            As[t] = (float)(shb[t] - mint) / (float)(n - 1);   // cdftgt
        }
        __syncthreads();
        {
            int mins = sha[0];
            float x = (float)(sha[t] - mins) / (float)(n - 1); // cdfsrc
            // upper_bound on sorted cdftgt; edges overridden below
            int lo = 0, hi = NBINS - 1;
            while (lo < hi) { int mid = (lo + hi) >> 1; if (As[mid] > x) hi = mid; else lo = mid + 1; }
            int ind1 = lo;
            int ind0 = max(ind1 - 1, 0);
            float dx0 = As[ind0], dx1 = As[ind1];
            float dy0 = fsv[ind0], dy1 = fsv[ind1];
            float dnm = dx1 - dx0;
            float sd  = (dnm == 0.0f) ? 1.0f : dnm;
            float interp = dy0 + (dy1 - dy0) * (x - dx0) / sd;
            float res = (x <= As[0]) ? fsv[0]
                      : ((x >= As[NBINS - 1]) ? fsv[NBINS - 1] : interp);
            pmS[t] = res;
            g_pxmap[t] = res;
        }
        __threadfence();
        __syncthreads();
        if (t == 0) g_release = 1;
    } else {
        if (t == 0) {
            while (g_release == 0) __nanosleep(32);
            __threadfence();   // acquire
        }
        __syncthreads();
        pmS[t] = __ldcg(&g_pxmap[t]);
    }
    __syncthreads();

    // ---- slope/intercept tables ----
    if (t > 0) {
        float d = fsv[t] - fsv[t - 1];          // strictly > 0
        float a = (pmS[t] - pmS[t - 1]) / d;
        As[t] = a;
        Bs[t] = pmS[t - 1] - a * fsv[t - 1];
    }
    __syncthreads();

    // ---------------- Phase 3: apply ----------------
    const float pm0 = pmS[0], pm255 = pmS[NBINS - 1];
    const float fs0 = fsv[0], fs255 = fsv[NBINS - 1];

    #pragma unroll
    for (int k = 0; k < KQ; ++k) {
        int q = gtid + k * nth;
        if (q < nq) {
            float4 v;
            v.x = apply1(xr[4 * k + 0], fsv, As, Bs, pm0, pm255, fs0, fs255);
            v.y = apply1(xr[4 * k + 1], fsv, As, Bs, pm0, pm255, fs0, fs255);
            v.z = apply1(xr[4 * k + 2], fsv, As, Bs, pm0, pm255, fs0, fs255);
            v.w = apply1(xr[4 * k + 3], fsv, As, Bs, pm0, pm255, fs0, fs255);
            o4[q] = v;
        }
    }
    for (int q = gtid + KQ * nth; q < nq; q += nth) {
        float4 v = o4[q];   // spilled x values
        v.x = apply1(v.x, fsv, As, Bs, pm0, pm255, fs0, fs255);
        v.y = apply1(v.y, fsv, As, Bs, pm0, pm255, fs0, fs255);
        v.z = apply1(v.z, fsv, As, Bs, pm0, pm255, fs0, fs255);
        v.w = apply1(v.w, fsv, As, Bs, pm0, pm255, fs0, fs255);
        o4[q] = v;
    }
    if (tidx < n) out[tidx] = apply1(xtail, fsv, As, Bs, pm0, pm255, fs0, fs255);

    // ---------------- Reset barrier state for next replay ----------------
    __syncthreads();
    if (t == 0) {
        __threadfence();
        int old = atomicAdd(&g_done1, 1);
        if (old == (int)gridDim.x - 1) {
            g_done0 = 0;
            g_done1 = 0;
            __threadfence();
            g_release = 0;
        }
    }
}

extern "C" void kernel_launch(void* const* d_in, const int* in_sizes, int n_in,
                              void* d_out, int out_size) {
    const float* src = (const float*)d_in[0];
    const float* tgt = (const float*)d_in[1];
    float* out = (float*)d_out;
    int n = in_sizes[0] / 3;   // H*W pixels
    int nq = n >> 2;

    // enough blocks for 6 CTAs/SM; each thread still holds <= KQ quads
    int blocks = (nq + TPB - 1) / TPB;      // 1 quad per thread if possible
    if (blocks > MAXB) blocks = MAXB;       // 6 CTAs/SM cap; KQ=2 covers rest
    if (blocks < 1) blocks = 1;
    // guarantee capacity: blocks*TPB*KQ >= nq, else overflow loop handles it
    k_fused<<<blocks, TPB>>>(src, tgt, out, n);
}